// round 1
// baseline (speedup 1.0000x reference)
#include <cuda_runtime.h>
#include <math.h>

// Problem constants
#define N_TOT 8192          // B*T*H*W = 8*16*8*8
#define F_DIM 128
#define TBLK  64            // N_TOT / 128 tile blocks per dim

// Scratch (device globals: allocation-free per harness rules)
__device__ float g_xnT[F_DIM * N_TOT];   // normalized feats, transposed [F][N] (4 MB)
__device__ float g_part[TBLK * TBLK];    // per-block partial exp-sums

// ---------------------------------------------------------------------------
// Kernel 1: row-normalize. feats[n,f] = x[b, f, thw], n = b*1024 + thw.
// Writes x_norm transposed: g_xnT[f*N + n] (coalesced in n).
// ---------------------------------------------------------------------------
__global__ void normalize_kernel(const float* __restrict__ x) {
    int n = blockIdx.x * blockDim.x + threadIdx.x;
    if (n >= N_TOT) return;
    int b   = n >> 10;        // n / 1024
    int thw = n & 1023;
    const float* base = x + (size_t)b * 131072 + thw;   // b*F*1024 + thw

    float ss = 0.f;
#pragma unroll 16
    for (int f = 0; f < F_DIM; ++f) {
        float v = base[(size_t)f * 1024];
        ss += v * v;
    }
    float nrm = fmaxf(sqrtf(ss), 1e-12f);   // matches F.normalize eps semantics
    float rn  = 1.0f / nrm;
#pragma unroll 16
    for (int f = 0; f < F_DIM; ++f) {
        g_xnT[f * N_TOT + n] = base[(size_t)f * 1024] * rn;
    }
}

// ---------------------------------------------------------------------------
// Kernel 2: fused SYRK-like GEMM + exp + sum.
// C tile = 128x128 per block, K = 128 in 4 chunks of 32. Only bj >= bi is
// computed (symmetry); off-diagonal block tiles weighted x2, diagonal block
// tiles skip i==j elements. Per-block sum -> g_part[bj*64+bi].
// ---------------------------------------------------------------------------
#define BM 128
#define BN 128
#define BK 32

__global__ void __launch_bounds__(256) simexp_kernel() {
    const int bi = blockIdx.x;
    const int bj = blockIdx.y;
    const int lin = bj * TBLK + bi;

    if (bj < bi) {                      // lower triangle: contribute 0
        if (threadIdx.x == 0) g_part[lin] = 0.f;
        return;
    }

    __shared__ float As[BK][BM];
    __shared__ float Bs[BK][BN];
    __shared__ float red[8];

    const int tid = threadIdx.x;
    const int tx  = tid & 15;           // 16 cols of threads
    const int ty  = tid >> 4;           // 16 rows of threads

    float acc[8][8];
#pragma unroll
    for (int u = 0; u < 8; ++u)
#pragma unroll
        for (int v = 0; v < 8; ++v) acc[u][v] = 0.f;

    const float* Abase = g_xnT + bi * BM;
    const float* Bbase = g_xnT + bj * BN;

    for (int kt = 0; kt < F_DIM; kt += BK) {
        // cooperative load: 32 rows x 128 floats per tile = 1024 float4
#pragma unroll
        for (int j = 0; j < 4; ++j) {
            int idx = tid + j * 256;            // 0..1023
            int k   = idx >> 5;                 // row in tile (0..31)
            int i4  = (idx & 31) << 2;          // float offset (0..124)
            *(float4*)&As[k][i4] = *(const float4*)&Abase[(size_t)(kt + k) * N_TOT + i4];
            *(float4*)&Bs[k][i4] = *(const float4*)&Bbase[(size_t)(kt + k) * N_TOT + i4];
        }
        __syncthreads();

#pragma unroll
        for (int k = 0; k < BK; ++k) {
            float a[8], bf[8];
            *(float4*)&a[0]  = *(float4*)&As[k][ty * 4];
            *(float4*)&a[4]  = *(float4*)&As[k][64 + ty * 4];
            *(float4*)&bf[0] = *(float4*)&Bs[k][tx * 4];
            *(float4*)&bf[4] = *(float4*)&Bs[k][64 + tx * 4];
#pragma unroll
            for (int u = 0; u < 8; ++u)
#pragma unroll
                for (int v = 0; v < 8; ++v)
                    acc[u][v] = fmaf(a[u], bf[v], acc[u][v]);
        }
        __syncthreads();
    }

    // Epilogue: exp(sim/T) and accumulate, skipping diagonal elements.
    const bool diagblk = (bi == bj);
    float s = 0.f;
#pragma unroll
    for (int u = 0; u < 8; ++u) {
        int roff = (u < 4) ? (ty * 4 + u) : (64 + ty * 4 + (u - 4));
#pragma unroll
        for (int v = 0; v < 8; ++v) {
            int coff = (v < 4) ? (tx * 4 + v) : (64 + tx * 4 + (v - 4));
            if (diagblk && roff == coff) continue;   // exclude i==j
            s += __expf(acc[u][v] * 10.f);           // /TEMPERATURE
        }
    }
    if (!diagblk) s *= 2.f;                          // symmetry weight

    // block reduction (warp shuffle + smem)
#pragma unroll
    for (int off = 16; off > 0; off >>= 1)
        s += __shfl_down_sync(0xFFFFFFFFu, s, off);
    if ((tid & 31) == 0) red[tid >> 5] = s;
    __syncthreads();
    if (tid == 0) {
        float t = 0.f;
#pragma unroll
        for (int w = 0; w < 8; ++w) t += red[w];
        g_part[lin] = t;
    }
}

// ---------------------------------------------------------------------------
// Kernel 3: deterministic final reduction + log.
// ---------------------------------------------------------------------------
__global__ void finalize_kernel(float* __restrict__ out) {
    __shared__ float red[8];
    float s = 0.f;
    for (int i = threadIdx.x; i < TBLK * TBLK; i += 256) s += g_part[i];
#pragma unroll
    for (int off = 16; off > 0; off >>= 1)
        s += __shfl_down_sync(0xFFFFFFFFu, s, off);
    if ((threadIdx.x & 31) == 0) red[threadIdx.x >> 5] = s;
    __syncthreads();
    if (threadIdx.x == 0) {
        float t = 0.f;
#pragma unroll
        for (int w = 0; w < 8; ++w) t += red[w];
        out[0] = logf(t);   // NEGATIVE_WEIGHT = 1.0
    }
}

extern "C" void kernel_launch(void* const* d_in, const int* in_sizes, int n_in,
                              void* d_out, int out_size) {
    const float* x = (const float*)d_in[0];
    float* out = (float*)d_out;
    (void)in_sizes; (void)n_in; (void)out_size;

    normalize_kernel<<<N_TOT / 256, 256>>>(x);
    dim3 grid(TBLK, TBLK);
    simexp_kernel<<<grid, 256>>>();
    finalize_kernel<<<1, 256>>>(out);
}

// round 3
// speedup vs baseline: 4.5024x; 4.5024x over previous
#include <cuda_runtime.h>
#include <cuda_bf16.h>
#include <math.h>
#include <stdint.h>

#define N_TOT 8192
#define F_DIM 128
#define TBLK  64                 // 8192 / 128
#define NTILES (TBLK*(TBLK+1)/2) // 2080 upper-triangle tiles
#define ROWB  272                // padded smem row bytes (128 bf16 + 8 pad)
#define SM_TILE (128 * ROWB)     // 34816 bytes per tile
#define SM_TOTAL (2 * SM_TILE)   // 69632

// Device scratch (allocation-free rules)
__device__ __nv_bfloat16 g_xb[N_TOT * F_DIM];   // normalized feats [N][F] bf16 row-major
__device__ float g_part[NTILES];

__device__ __forceinline__ uint32_t smem_u32(const void* p) {
    uint32_t a;
    asm("{ .reg .u64 t; cvta.to.shared.u64 t, %1; cvt.u32.u64 %0, t; }" : "=r"(a) : "l"(p));
    return a;
}
__device__ __forceinline__ float ex2a(float x) {
    float y; asm("ex2.approx.f32 %0, %1;" : "=f"(y) : "f"(x)); return y;
}

// ---------------------------------------------------------------------------
// Kernel 1: normalize + bf16 convert, SMEM-staged for full coalescing.
// x layout (B=8, F=128, THW=1024), n = b*1024 + thw. Block: 64 consecutive n.
// ---------------------------------------------------------------------------
__global__ void __launch_bounds__(256) normalize_kernel(const float* __restrict__ x) {
    __shared__ float sm[F_DIM * 65];
    __shared__ float ssp[4][64];
    __shared__ float rn[64];

    const int tid = threadIdx.x;
    const int n0  = blockIdx.x * 64;
    const int b   = n0 >> 10;
    const int thw0 = n0 & 1023;
    const float* base = x + (size_t)b * 131072 + thw0;

#pragma unroll
    for (int it = 0; it < 32; ++it) {
        int idx = it * 256 + tid;
        int c = idx & 63;
        int f = idx >> 6;
        sm[f * 65 + c] = base[(size_t)f * 1024 + c];
    }
    __syncthreads();
    {
        int r = tid & 63, part = tid >> 6;
        float ss = 0.f;
#pragma unroll
        for (int f = part * 32; f < part * 32 + 32; ++f) {
            float v = sm[f * 65 + r];
            ss += v * v;
        }
        ssp[part][r] = ss;
    }
    __syncthreads();
    if (tid < 64) {
        float ss = ssp[0][tid] + ssp[1][tid] + ssp[2][tid] + ssp[3][tid];
        rn[tid] = 1.0f / fmaxf(sqrtf(ss), 1e-12f);
    }
    __syncthreads();
    __nv_bfloat16* out = g_xb + (size_t)n0 * F_DIM;
#pragma unroll
    for (int it = 0; it < 32; ++it) {
        int idx = it * 256 + tid;
        int f = idx & 127;
        int r = idx >> 7;
        out[(size_t)r * F_DIM + f] = __float2bfloat16(sm[f * 65 + r] * rn[r]);
    }
}

// ---------------------------------------------------------------------------
// Kernel 2: HMMA (mma.sync bf16) 128x128x128 tile + fused exp-sum epilogue.
// 8 warps, warp tile 64x32. Upper-triangle linear grid; diag tiles alias B=A.
// ---------------------------------------------------------------------------
__global__ void __launch_bounds__(256) simexp_kernel() {
    extern __shared__ char smem[];
    const int tid  = threadIdx.x;
    const int wid  = tid >> 5;
    const int lane = tid & 31;

    // linear tile id -> (bi, bj), bj >= bi; start(bi) = bi*(129-bi)/2
    int t = blockIdx.x;
    int bi = (int)((129.0f - sqrtf(16641.0f - 8.0f * (float)t)) * 0.5f);
    while ((bi + 1) * (129 - (bi + 1)) / 2 <= t) ++bi;
    while (bi * (129 - bi) / 2 > t) --bi;
    const int bj = bi + (t - bi * (129 - bi) / 2);
    const bool diag = (bi == bj);

    // --- cooperative tile loads: 128 rows x 256B, padded rows of 272B ---
    {
        const uint4* gA = (const uint4*)(g_xb + (size_t)bi * 128 * F_DIM);
#pragma unroll
        for (int it = 0; it < 8; ++it) {
            int idx = it * 256 + tid;
            int r = idx >> 4, q = idx & 15;
            *(uint4*)(smem + r * ROWB + q * 16) = gA[idx];
        }
        if (!diag) {
            const uint4* gB = (const uint4*)(g_xb + (size_t)bj * 128 * F_DIM);
#pragma unroll
            for (int it = 0; it < 8; ++it) {
                int idx = it * 256 + tid;
                int r = idx >> 4, q = idx & 15;
                *(uint4*)(smem + SM_TILE + r * ROWB + q * 16) = gB[idx];
            }
        }
    }
    __syncthreads();

    const uint32_t aBase = smem_u32(smem);
    const uint32_t bBase = diag ? aBase : (aBase + SM_TILE);

    const int wm = (wid >> 2) * 64;   // warp m offset
    const int wn = (wid & 3) * 32;    // warp n offset
    const int g  = lane >> 3;         // ldmatrix quad group
    const int lr = lane & 7;

    float acc[4][4][4];
#pragma unroll
    for (int mt = 0; mt < 4; ++mt)
#pragma unroll
        for (int nt = 0; nt < 4; ++nt)
#pragma unroll
            for (int c = 0; c < 4; ++c) acc[mt][nt][c] = 0.f;

#pragma unroll
    for (int kc = 0; kc < 8; ++kc) {
        // A fragments: 4 m-tiles of 16x16
        uint32_t a[4][4];
#pragma unroll
        for (int mt = 0; mt < 4; ++mt) {
            int row = wm + mt * 16 + (g & 1) * 8 + lr;
            uint32_t addr = aBase + row * ROWB + kc * 32 + (g >> 1) * 16;
            asm volatile("ldmatrix.sync.aligned.m8n8.x4.shared.b16 {%0,%1,%2,%3}, [%4];"
                         : "=r"(a[mt][0]), "=r"(a[mt][1]), "=r"(a[mt][2]), "=r"(a[mt][3])
                         : "r"(addr));
        }
        // B fragments: 2 x ldmatrix.x4, each covers two n8 frags
        uint32_t bf[2][4];
#pragma unroll
        for (int np = 0; np < 2; ++np) {
            int row = wn + np * 16 + (g >> 1) * 8 + lr;
            uint32_t addr = bBase + row * ROWB + kc * 32 + (g & 1) * 16;
            asm volatile("ldmatrix.sync.aligned.m8n8.x4.shared.b16 {%0,%1,%2,%3}, [%4];"
                         : "=r"(bf[np][0]), "=r"(bf[np][1]), "=r"(bf[np][2]), "=r"(bf[np][3])
                         : "r"(addr));
        }
#pragma unroll
        for (int mt = 0; mt < 4; ++mt)
#pragma unroll
            for (int nt = 0; nt < 4; ++nt) {
                uint32_t b0 = bf[nt >> 1][(nt & 1) * 2];
                uint32_t b1 = bf[nt >> 1][(nt & 1) * 2 + 1];
                asm volatile(
                    "mma.sync.aligned.m16n8k16.row.col.f32.bf16.bf16.f32 "
                    "{%0,%1,%2,%3}, {%4,%5,%6,%7}, {%8,%9}, {%0,%1,%2,%3};"
                    : "+f"(acc[mt][nt][0]), "+f"(acc[mt][nt][1]),
                      "+f"(acc[mt][nt][2]), "+f"(acc[mt][nt][3])
                    : "r"(a[mt][0]), "r"(a[mt][1]), "r"(a[mt][2]), "r"(a[mt][3]),
                      "r"(b0), "r"(b1));
            }
    }

    // --- epilogue: exp(sim * 10) and sum, skipping i==j on diag tiles ---
    const int lrow = lane >> 2;
    const int lcol = (lane & 3) * 2;
    const float SC = 14.4269504088896f;   // 10 / ln(2)
    float s = 0.f;
#pragma unroll
    for (int mt = 0; mt < 4; ++mt)
#pragma unroll
        for (int nt = 0; nt < 4; ++nt)
#pragma unroll
            for (int c = 0; c < 4; ++c) {
                int r_ = wm + mt * 16 + ((c >> 1) << 3) + lrow;
                int c_ = wn + nt * 8 + lcol + (c & 1);
                if (diag && r_ == c_) continue;
                s += ex2a(acc[mt][nt][c] * SC);
            }
    if (!diag) s *= 2.f;

    __shared__ float red[8];
#pragma unroll
    for (int off = 16; off > 0; off >>= 1)
        s += __shfl_down_sync(0xFFFFFFFFu, s, off);
    if (lane == 0) red[wid] = s;
    __syncthreads();
    if (tid == 0) {
        float tsum = 0.f;
#pragma unroll
        for (int w = 0; w < 8; ++w) tsum += red[w];
        g_part[blockIdx.x] = tsum;
    }
}

// ---------------------------------------------------------------------------
// Kernel 3: deterministic final reduction + log
// ---------------------------------------------------------------------------
__global__ void __launch_bounds__(256) finalize_kernel(float* __restrict__ out) {
    __shared__ float red[8];
    float s = 0.f;
    for (int i = threadIdx.x; i < NTILES; i += 256) s += g_part[i];
#pragma unroll
    for (int off = 16; off > 0; off >>= 1)
        s += __shfl_down_sync(0xFFFFFFFFu, s, off);
    if ((threadIdx.x & 31) == 0) red[threadIdx.x >> 5] = s;
    __syncthreads();
    if (threadIdx.x == 0) {
        float tsum = 0.f;
#pragma unroll
        for (int w = 0; w < 8; ++w) tsum += red[w];
        out[0] = logf(tsum);
    }
}

extern "C" void kernel_launch(void* const* d_in, const int* in_sizes, int n_in,
                              void* d_out, int out_size) {
    const float* x = (const float*)d_in[0];
    float* out = (float*)d_out;
    (void)in_sizes; (void)n_in; (void)out_size;

    cudaFuncSetAttribute(simexp_kernel, cudaFuncAttributeMaxDynamicSharedMemorySize, SM_TOTAL);

    normalize_kernel<<<N_TOT / 64, 256>>>(x);
    simexp_kernel<<<NTILES, 256, SM_TOTAL>>>();
    finalize_kernel<<<1, 256>>>(out);
}